// round 1
// baseline (speedup 1.0000x reference)
#include <cuda_runtime.h>

#define NMAX 100000
#define HID 256
#define EMB 128

// ---------------- scratch (static device globals; no allocation) -------------
__device__ int                 g_degi[NMAX];          // degree incl. self loop
__device__ float               g_dis[NMAX];           // 1/sqrt(deg)
__device__ unsigned long long  g_tq[NMAX];            // fixed-point sum of dis[src] into dst
__device__ float               g_s[NMAX];             // per-node scalar
__device__ float               g_thr[HID];            // sorted relu breakpoints
__device__ __align__(16) float2 g_tab[(HID + 1) * EMB]; // per-interval (A, C) pairs
__device__ int                 g_e32;                 // 1 if edge_index is int32-packed

// ---------------- edge dtype detection ---------------------------------------
__global__ void k_detect(const void* __restrict__ edges) {
    const long long* p = (const long long*)edges;
    int is32 = 0;
    #pragma unroll
    for (int i = 0; i < 4; i++) {
        unsigned long long v = (unsigned long long)p[i];
        if (v >= (1ull << 32)) is32 = 1;  // hi word nonzero => two packed int32 node ids
    }
    g_e32 = is32;
}

// ---------------- init --------------------------------------------------------
__global__ void k_init(int N) {
    int n = blockIdx.x * blockDim.x + threadIdx.x;
    if (n < N) { g_degi[n] = 1; g_tq[n] = 0ull; }
}

// ---------------- pass 1: degree over dst ------------------------------------
__global__ void k_deg(const void* __restrict__ edges, int E) {
    int e = blockIdx.x * blockDim.x + threadIdx.x;
    if (e >= E) return;
    int dst;
    if (g_e32) dst = ((const int*)edges)[E + e];
    else       dst = (int)((const long long*)edges)[E + e];
    atomicAdd(&g_degi[dst], 1);
}

__global__ void k_dis(int N) {
    int n = blockIdx.x * blockDim.x + threadIdx.x;
    if (n < N) g_dis[n] = rsqrtf((float)g_degi[n]);
}

// ---------------- pass 2: t[dst] += dis[src]  (fixed-point, deterministic) ---
__global__ void k_scat(const void* __restrict__ edges, int E) {
    int e = blockIdx.x * blockDim.x + threadIdx.x;
    if (e >= E) return;
    int src, dst;
    if (g_e32) {
        const int* p = (const int*)edges;
        src = p[e]; dst = p[E + e];
    } else {
        const long long* p = (const long long*)edges;
        src = (int)p[e]; dst = (int)p[E + e];
    }
    float d = g_dis[src];
    unsigned long long q = (unsigned long long)(d * 4294967296.0f);  // dis in (0,1]
    atomicAdd(&g_tq[dst], q);
}

__global__ void k_s(int N) {
    int n = blockIdx.x * blockDim.x + threadIdx.x;
    if (n < N) {
        float t = (float)g_tq[n] * 2.3283064365386963e-10f;  // * 2^-32
        float d = g_dis[n];
        g_s[n] = d * (t + d);
    }
}

// ---------------- build breakpoint tables (single block, 256 threads) --------
// relu(s*w+b): for s>0, active set changes at t_h = -b/w when (w>0,b<0) [+] or
// (w<0,b>0) [-]. Base set at s->0+: b>0 (or b==0 && w>0). Each toggled term is
// exactly 0 at its breakpoint, so interval boundary handling is value-exact.
__global__ void k_build(const float* __restrict__ W1, const float* __restrict__ b1,
                        const float* __restrict__ W2, const float* __restrict__ b2) {
    __shared__ float key[HID];
    __shared__ int   idx[HID];
    __shared__ float sw[HID];
    __shared__ float sb[HID];
    int t = threadIdx.x;
    float w = W1[t], b = b1[t];
    sw[t] = w; sb[t] = b;
    float thr = 3.0e38f;  // no crossing in (0, inf)
    if ((w > 0.f && b < 0.f) || (w < 0.f && b > 0.f)) thr = -b / w;
    key[t] = thr; idx[t] = t;
    __syncthreads();

    // bitonic sort ascending (key, idx), 256 elems / 256 threads
    for (int k = 2; k <= HID; k <<= 1) {
        for (int j = k >> 1; j > 0; j >>= 1) {
            int p = t ^ j;
            if (p > t) {
                bool up = ((t & k) == 0);
                float ka = key[t], kb = key[p];
                if ((ka > kb) == up) {
                    key[t] = kb; key[p] = ka;
                    int ia = idx[t]; idx[t] = idx[p]; idx[p] = ia;
                }
            }
            __syncthreads();
        }
    }
    g_thr[t] = key[t];

    if (t < EMB) {
        // base interval (0, thr_min)
        float a = 0.f, c = b2[t];
        for (int h = 0; h < HID; h++) {
            float wh = sw[h], bh = sb[h];
            bool act = (bh > 0.f) || (bh == 0.f && wh > 0.f);
            if (act) {
                float w2 = W2[h * EMB + t];
                a = fmaf(wh, w2, a);
                c = fmaf(bh, w2, c);
            }
        }
        g_tab[t] = make_float2(a, c);
        // sweep across sorted breakpoints
        for (int k = 1; k <= HID; k++) {
            int h = idx[k - 1];
            float wh = sw[h], bh = sb[h];
            float d = (wh > 0.f && bh < 0.f) ? 1.f : ((wh < 0.f && bh > 0.f) ? -1.f : 0.f);
            if (d != 0.f) {
                float w2 = W2[h * EMB + t];
                a = fmaf(d * wh, w2, a);
                c = fmaf(d * bh, w2, c);
            }
            g_tab[k * EMB + t] = make_float2(a, c);
        }
    }
}

// ---------------- per-node output: binary search + 128 affine sigmoids -------
__global__ void k_out(float* __restrict__ out, int N) {
    __shared__ float sthr[HID];
    for (int i = threadIdx.x; i < HID; i += blockDim.x) sthr[i] = g_thr[i];
    __syncthreads();

    int n = blockIdx.x * blockDim.x + threadIdx.x;
    if (n >= N) return;
    float s = g_s[n];

    // k = count of thresholds < s  -> interval index
    int lo = 0, hi = HID;
    while (lo < hi) {
        int m = (lo + hi) >> 1;
        if (sthr[m] < s) lo = m + 1; else hi = m;
    }

    const float4* __restrict__ row4 = (const float4*)(g_tab + lo * EMB);
    #pragma unroll 4
    for (int jj = 0; jj < EMB / 2; jj++) {
        float4 v = __ldg(&row4[jj]);                 // (A_j, C_j, A_{j+1}, C_{j+1})
        float x0 = fmaf(s, v.x, v.y);
        float x1 = fmaf(s, v.z, v.w);
        float y0 = __fdividef(1.f, 1.f + __expf(-x0));
        float y1 = __fdividef(1.f, 1.f + __expf(-x1));
        int j = jj * 2;
        out[j * N + n]       = y0;
        out[(j + 1) * N + n] = y1;
    }
}

// ---------------- launch ------------------------------------------------------
extern "C" void kernel_launch(void* const* d_in, const int* in_sizes, int n_in,
                              void* d_out, int out_size) {
    const void*  edges = d_in[0];
    const float* W1    = (const float*)d_in[1];
    const float* b1    = (const float*)d_in[2];
    const float* W2    = (const float*)d_in[3];
    const float* b2    = (const float*)d_in[4];
    int E = in_sizes[0] / 2;
    int N = out_size / EMB;
    if (N > NMAX) N = NMAX;

    const int TB = 256;
    int gN = (N + TB - 1) / TB;
    int gE = (E + TB - 1) / TB;

    k_detect<<<1, 1>>>(edges);
    k_init  <<<gN, TB>>>(N);
    k_deg   <<<gE, TB>>>(edges, E);
    k_dis   <<<gN, TB>>>(N);
    k_scat  <<<gE, TB>>>(edges, E);
    k_s     <<<gN, TB>>>(N);
    k_build <<<1, HID>>>(W1, b1, W2, b2);
    k_out   <<<gN, TB>>>((float*)d_out, N);
}

// round 2
// speedup vs baseline: 1.1231x; 1.1231x over previous
#include <cuda_runtime.h>

#define NMAX 100000
#define HID 256
#define EMB 128

// ---------------- scratch (static device globals; no allocation) -------------
__device__ int            g_degi[NMAX];            // degree incl. self loop
__device__ unsigned int   g_tq[NMAX];              // fixed-point (2^25) sum of dis[src]
__device__ float          g_thr[HID];              // sorted relu breakpoints
__device__ __align__(16) float2 g_tab[(HID + 1) * EMB]; // per-interval (A, C)
__device__ int            g_e32;                   // 1 if edge_index is int32-packed

#define FXS 33554432.0f          // 2^25
#define FXI 2.9802322387695312e-08f  // 2^-25

// ---- K1: init deg/tq; last block: detect edge dtype + sort relu thresholds --
__global__ void k_init(const void* __restrict__ edges,
                       const float* __restrict__ W1, const float* __restrict__ b1,
                       int N) {
    if (blockIdx.x == gridDim.x - 1) {
        int t = threadIdx.x;
        if (t == 0) {
            const long long* p = (const long long*)edges;
            int is32 = 0;
            #pragma unroll
            for (int i = 0; i < 4; i++)
                if ((unsigned long long)p[i] >= (1ull << 32)) is32 = 1;
            g_e32 = is32;
        }
        // relu(s*w+b) crossing for s>0: thr=-b/w if (w>0,b<0) or (w<0,b>0)
        __shared__ float key[HID];
        float w = W1[t], b = b1[t];
        float thr = 3.0e38f;
        if ((w > 0.f && b < 0.f) || (w < 0.f && b > 0.f)) thr = -b / w;
        key[t] = thr;
        __syncthreads();
        for (int k = 2; k <= HID; k <<= 1) {
            for (int j = k >> 1; j > 0; j >>= 1) {
                int p = t ^ j;
                if (p > t) {
                    bool up = ((t & k) == 0);
                    float ka = key[t], kb = key[p];
                    if ((ka > kb) == up) { key[t] = kb; key[p] = ka; }
                }
                __syncthreads();
            }
        }
        g_thr[t] = key[t];
    } else {
        int n = blockIdx.x * blockDim.x + threadIdx.x;
        if (n < N) { g_degi[n] = 1; g_tq[n] = 0u; }
    }
}

// ---- K2: degree over dst (4 edges / thread, int4 loads) ----------------------
__global__ void k_deg(const void* __restrict__ edges, int E) {
    int i = (blockIdx.x * blockDim.x + threadIdx.x) * 4;
    if (i >= E) return;
    if (g_e32) {
        const int* p = (const int*)edges + E;  // dst half
        if (i + 4 <= E) {
            int4 v = *(const int4*)(p + i);
            atomicAdd(&g_degi[v.x], 1); atomicAdd(&g_degi[v.y], 1);
            atomicAdd(&g_degi[v.z], 1); atomicAdd(&g_degi[v.w], 1);
        } else {
            for (int j = i; j < E; j++) atomicAdd(&g_degi[p[j]], 1);
        }
    } else {
        const long long* p = (const long long*)edges + E;
        if (i + 4 <= E) {
            const int4* q = (const int4*)(p + i);
            int4 a = q[0], b = q[1];   // low words at .x / .z (little-endian)
            atomicAdd(&g_degi[a.x], 1); atomicAdd(&g_degi[a.z], 1);
            atomicAdd(&g_degi[b.x], 1); atomicAdd(&g_degi[b.z], 1);
        } else {
            for (int j = i; j < E; j++) atomicAdd(&g_degi[(int)p[j]], 1);
        }
    }
}

// ---- K3: build tables, one block per interval (257 blocks x 128 threads) ----
// Activity of term h over interval k is constant; evaluate at an interior
// representative. Toggled terms are exactly 0 at their breakpoints, so
// boundary handling is value-exact.
__global__ void k_tab(const float* __restrict__ W1, const float* __restrict__ b1,
                      const float* __restrict__ W2, const float* __restrict__ b2) {
    __shared__ float sw[HID], sb[HID];
    int j = threadIdx.x;
    int k = blockIdx.x;
    sw[j] = W1[j]; sw[j + 128] = W1[j + 128];
    sb[j] = b1[j]; sb[j + 128] = b1[j + 128];
    __syncthreads();

    float lo = (k == 0) ? 0.f : g_thr[k - 1];
    float hi = (k == HID) ? ((lo < 1e30f) ? fmaf(2.f, lo, 2.f) : 3.2e38f) : g_thr[k];
    float rep = 0.5f * lo + 0.5f * hi;

    float a = 0.f, c = b2[j];
    #pragma unroll 4
    for (int h = 0; h < HID; h++) {
        float w = sw[h], b = sb[h];
        if (fmaf(rep, w, b) > 0.f) {
            float w2 = __ldg(&W2[h * EMB + j]);
            a = fmaf(w, w2, a);
            c = fmaf(b, w2, c);
        }
    }
    g_tab[k * EMB + j] = make_float2(a, c);
}

// ---- K4: t[dst] += dis[src] (u32 fixed-point, deterministic; 4 edges/thr) ---
__device__ __forceinline__ void scat1(int src, int dst) {
    float d = rsqrtf((float)g_degi[src]);
    atomicAdd(&g_tq[dst], __float2uint_rn(d * FXS));
}
__global__ void k_scat(const void* __restrict__ edges, int E) {
    int i = (blockIdx.x * blockDim.x + threadIdx.x) * 4;
    if (i >= E) return;
    if (g_e32) {
        const int* ps = (const int*)edges;
        const int* pd = ps + E;
        if (i + 4 <= E) {
            int4 s = *(const int4*)(ps + i);
            int4 d = *(const int4*)(pd + i);
            scat1(s.x, d.x); scat1(s.y, d.y); scat1(s.z, d.z); scat1(s.w, d.w);
        } else {
            for (int j = i; j < E; j++) scat1(ps[j], pd[j]);
        }
    } else {
        const long long* ps = (const long long*)edges;
        const long long* pd = ps + E;
        if (i + 4 <= E) {
            const int4* qs = (const int4*)(ps + i);
            const int4* qd = (const int4*)(pd + i);
            int4 s0 = qs[0], s1 = qs[1], d0 = qd[0], d1 = qd[1];
            scat1(s0.x, d0.x); scat1(s0.z, d0.z);
            scat1(s1.x, d1.x); scat1(s1.z, d1.z);
        } else {
            for (int j = i; j < E; j++) scat1((int)ps[j], (int)pd[j]);
        }
    }
}

// ---- K5: per-node s + binary search + 128 affine sigmoids (2 nodes/thread) --
__global__ void k_out(float* __restrict__ out, int N) {
    __shared__ float sthr[HID];
    for (int i = threadIdx.x; i < HID; i += blockDim.x) sthr[i] = g_thr[i];
    __syncthreads();

    int n0 = (blockIdx.x * blockDim.x + threadIdx.x) * 2;
    if (n0 >= N) return;
    bool has2 = (n0 + 1 < N) && ((N & 1) == 0);
    int n1 = has2 ? n0 + 1 : n0;

    float d0 = rsqrtf((float)g_degi[n0]);
    float d1 = rsqrtf((float)g_degi[n1]);
    float s0 = d0 * ((float)g_tq[n0] * FXI + d0);
    float s1 = d1 * ((float)g_tq[n1] * FXI + d1);

    int lo0 = 0, hi0 = HID, lo1 = 0, hi1 = HID;
    #pragma unroll
    for (int it = 0; it < 8; it++) {
        int m0 = (lo0 + hi0) >> 1;
        if (sthr[m0] < s0) lo0 = m0 + 1; else hi0 = m0;
        int m1 = (lo1 + hi1) >> 1;
        if (sthr[m1] < s1) lo1 = m1 + 1; else hi1 = m1;
    }

    const float4* __restrict__ r0 = (const float4*)(g_tab + lo0 * EMB);
    const float4* __restrict__ r1 = (const float4*)(g_tab + lo1 * EMB);

    if (has2) {
        #pragma unroll 8
        for (int jj = 0; jj < EMB / 2; jj++) {
            float4 va = __ldg(&r0[jj]);
            float4 vb = __ldg(&r1[jj]);
            float xa0 = fmaf(s0, va.x, va.y), xa1 = fmaf(s0, va.z, va.w);
            float xb0 = fmaf(s1, vb.x, vb.y), xb1 = fmaf(s1, vb.z, vb.w);
            float ya0 = __fdividef(1.f, 1.f + __expf(-xa0));
            float ya1 = __fdividef(1.f, 1.f + __expf(-xa1));
            float yb0 = __fdividef(1.f, 1.f + __expf(-xb0));
            float yb1 = __fdividef(1.f, 1.f + __expf(-xb1));
            int j = jj * 2;
            *(float2*)&out[j * N + n0]       = make_float2(ya0, yb0);
            *(float2*)&out[(j + 1) * N + n0] = make_float2(ya1, yb1);
        }
    } else {
        #pragma unroll 8
        for (int jj = 0; jj < EMB / 2; jj++) {
            float4 va = __ldg(&r0[jj]);
            float xa0 = fmaf(s0, va.x, va.y), xa1 = fmaf(s0, va.z, va.w);
            int j = jj * 2;
            out[j * N + n0]       = __fdividef(1.f, 1.f + __expf(-xa0));
            out[(j + 1) * N + n0] = __fdividef(1.f, 1.f + __expf(-xa1));
        }
    }
}

// ---------------- launch ------------------------------------------------------
extern "C" void kernel_launch(void* const* d_in, const int* in_sizes, int n_in,
                              void* d_out, int out_size) {
    const void*  edges = d_in[0];
    const float* W1    = (const float*)d_in[1];
    const float* b1    = (const float*)d_in[2];
    const float* W2    = (const float*)d_in[3];
    const float* b2    = (const float*)d_in[4];
    int E = in_sizes[0] / 2;
    int N = out_size / EMB;
    if (N > NMAX) N = NMAX;

    const int TB = 256;
    int gN = (N + TB - 1) / TB;
    int gE = (E + TB * 4 - 1) / (TB * 4);
    int gO = (N + TB * 2 - 1) / (TB * 2);

    k_init<<<gN + 1, TB>>>(edges, W1, b1, N);
    k_deg <<<gE, TB>>>(edges, E);
    k_tab <<<HID + 1, EMB>>>(W1, b1, W2, b2);
    k_scat<<<gE, TB>>>(edges, E);
    k_out <<<gO, TB>>>((float*)d_out, N);
}